// round 1
// baseline (speedup 1.0000x reference)
#include <cuda_runtime.h>

// Problem constants
#define B_  16
#define C_  4
#define NP_ 256
#define XD_ 128
#define UD_ 32
#define T_  20
#define PD_ 64

#define IMG_ELEMS   (B_*C_*128*128*T_)      // 20971520
#define XPRED_OFF   IMG_ELEMS
#define XPRED_ELEMS (B_*C_*NP_*XD_*T_)      // 41943040
#define XU_OFF      (XPRED_OFF + XPRED_ELEMS) // 62914560

#define CTAS_PER_C 148
#define THREADS    192

// shared memory layout (floats)
#define AS_PITCH 129
#define CS_PITCH 65
#define AS_OFF 0
#define CS_OFF (128*AS_PITCH)               // 16512
#define XS_OFF (CS_OFF + 128*CS_PITCH)      // 24832  (byte addr %16 == 0)
#define XP_OFF (XS_OFF + XD_*T_)            // 27392  (byte addr %16 == 0)
#define SMEM_FLOATS (XP_OFF + XD_*T_)       // 29952 floats = 119808 B

// packed f32x2 FMA (Blackwell PTX-only pattern; doubles fp32 FMA rate)
#define FMA2(acc, a2, b2) \
    asm("fma.rn.f32x2 %0, %1, %2, %0;" : "+l"(acc) : "l"(a2), "l"(b2))

__device__ __forceinline__ unsigned long long pk2(float lo, float hi) {
    unsigned long long r;
    asm("mov.b64 %0, {%1, %2};" : "=l"(r) : "f"(lo), "f"(hi));
    return r;
}

union V2x2 { float4 f; unsigned long long u[2]; };

// Row GEMV over 20 time columns with packed-f32x2 accumulation.
// mat row access As[j*pitch + i] is conflict-free (odd pitch, consecutive i per warp).
// src rows are broadcast reads (all lanes same address).
__device__ __forceinline__ void gemv20(const float* __restrict__ mat, int pitch, int i,
                                       const float* __restrict__ src,
                                       unsigned long long acc2[10]) {
    #pragma unroll 4
    for (int j = 0; j < XD_; j++) {
        float a = mat[j*pitch + i];
        unsigned long long a2 = pk2(a, a);
        const float4* row = (const float4*)(src + j*T_);
        #pragma unroll
        for (int q = 0; q < 5; q++) {
            V2x2 vv; vv.f = row[q];
            FMA2(acc2[2*q],   a2, vv.u[0]);
            FMA2(acc2[2*q+1], a2, vv.u[1]);
        }
    }
}

extern __shared__ float smem[];

__global__ __launch_bounds__(THREADS, 1)
void fista_main(const float* __restrict__ X, const float* __restrict__ x0,
                const float* __restrict__ A, const float* __restrict__ Cm,
                float* __restrict__ out)
{
    const int c    = blockIdx.x / CTAS_PER_C;
    const int slot = blockIdx.x % CTAS_PER_C;
    const int tid  = threadIdx.x;

    float* As = smem + AS_OFF;
    float* Cs = smem + CS_OFF;
    float* xs = smem + XS_OFF;   // xs[j][t]   = X[b,c,p,j,t]
    float* xp = smem + XP_OFF;   // xp[j][t]   = prev (t==0 -> x0, else X[...,t-1])

    // Stage A[c] and C[c] transposed: As[j][i], Cs[j][i]; odd pitch kills bank conflicts.
    for (int idx = tid; idx < XD_*XD_; idx += THREADS) {
        int i = idx >> 7, j = idx & 127;
        As[j*AS_PITCH + i] = A[c*XD_*XD_ + idx];
    }
    for (int idx = tid; idx < PD_*XD_; idx += THREADS) {
        int i = idx >> 7, j = idx & 127;
        Cs[j*CS_PITCH + i] = Cm[c*PD_*XD_ + idx];
    }

    for (int pp = slot; pp < B_*NP_; pp += CTAS_PER_C) {
        const int b = pp >> 8;
        const int p = pp & 255;
        const int bc = b*C_ + c;
        const int base   = (bc*NP_ + p) * (XD_*T_);
        const int x0base = (bc*NP_ + p) * XD_;

        __syncthreads();  // prior compute done (and A/C staged on first iter)
        for (int idx = tid; idx < XD_*T_; idx += THREADS) {
            float v = X[base + idx];
            xs[idx] = v;
            int j = idx / T_;
            int t = idx - j*T_;
            if (t < T_-1) xp[idx + 1] = v;          // shift right by one timestep
            if (t == 0)   xp[idx]     = x0[x0base + j];
        }
        __syncthreads();

        if (tid < XD_) {
            // X_pred row i = tid over all 20 t
            const int i = tid;
            unsigned long long acc2[10];
            #pragma unroll
            for (int q = 0; q < 10; q++) acc2[q] = 0ull;
            gemv20(As, AS_PITCH, i, xp, acc2);
            float4* dst = (float4*)(out + XPRED_OFF + (long)((bc*NP_ + p)*XD_ + i)*T_);
            #pragma unroll
            for (int q = 0; q < 5; q++) {
                V2x2 o; o.u[0] = acc2[2*q]; o.u[1] = acc2[2*q+1];
                dst[q] = o.f;
            }
        } else {
            // recon row i = tid-128 (0..63), scattered to pixel-shuffled img layout
            const int i = tid - XD_;
            unsigned long long acc2[10];
            #pragma unroll
            for (int q = 0; q < 10; q++) acc2[q] = 0ull;
            gemv20(Cs, CS_PITCH, i, xs, acc2);
            const int py = i >> 3, px = i & 7;
            const int gy = p >> 4, gx = p & 15;
            const long off = ((long)(bc*128 + gy*8 + py)*128 + gx*8 + px) * T_;
            float4* dst = (float4*)(out + off);
            #pragma unroll
            for (int q = 0; q < 5; q++) {
                V2x2 o; o.u[0] = acc2[2*q]; o.u[1] = acc2[2*q+1];
                dst[q] = o.f;
            }
        }
    }
}

// X_U: one thread per (b,c,i,t): S = sum_p |X|, Bu = B2[c,i,:] . U[b,c,:,t],
// out = 0.05*(1+exp(-Bu)) * S.  Deterministic serial sums (no atomics).
__global__ __launch_bounds__(256)
void fista_xu(const float* __restrict__ X, const float* __restrict__ U,
              const float* __restrict__ Bm, float* __restrict__ out)
{
    const int idx = blockIdx.x * blockDim.x + threadIdx.x;  // [0, 163840)
    const int t  = idx % T_;
    const int i  = (idx / T_) & (XD_-1);
    const int bc = idx / (XD_*T_);
    const int c  = bc & (C_-1);

    const float* xptr = X + (long)bc*NP_*XD_*T_ + i*T_ + t;
    float S = 0.f;
    #pragma unroll 4
    for (int p = 0; p < NP_; p++) S += fabsf(xptr[(long)p*XD_*T_]);

    const float* uptr = U + bc*UD_*T_ + t;
    const float* brow = Bm + (c*XD_ + i)*UD_;
    float bu = 0.f;
    #pragma unroll
    for (int j = 0; j < UD_; j++) bu += brow[j] * uptr[j*T_];

    out[XU_OFF + idx] = 0.05f * (1.f + expf(-bu)) * S;
}

extern "C" void kernel_launch(void* const* d_in, const int* in_sizes, int n_in,
                              void* d_out, int out_size)
{
    const float* X  = (const float*)d_in[0];
    const float* U  = (const float*)d_in[1];
    const float* x0 = (const float*)d_in[2];
    const float* A  = (const float*)d_in[3];
    const float* Bm = (const float*)d_in[4];
    const float* Cm = (const float*)d_in[5];
    float* out = (float*)d_out;

    // Opt in to >48KB dynamic smem (idempotent; not a stream op, capture-safe).
    cudaFuncSetAttribute(fista_main, cudaFuncAttributeMaxDynamicSharedMemorySize,
                         SMEM_FLOATS * (int)sizeof(float));

    fista_main<<<C_*CTAS_PER_C, THREADS, SMEM_FLOATS*sizeof(float)>>>(X, x0, A, Cm, out);
    fista_xu<<<(B_*C_*XD_*T_)/256, 256>>>(X, U, Bm, out);
}

// round 4
// speedup vs baseline: 1.9985x; 1.9985x over previous
#include <cuda_runtime.h>

// ---------------- problem constants ----------------
#define B_  16
#define C_  4
#define NP_ 256
#define XD_ 128
#define UD_ 32
#define T_  20
#define PD_ 64

#define IMG_ELEMS   (B_*C_*128*128*T_)               // 20971520
#define XPRED_OFF   IMG_ELEMS
#define XU_OFF      (XPRED_OFF + B_*C_*NP_*XD_*T_)   // 62914560

// ---------------- GEMM tiling ----------------
#define GN       8                 // (b,p) groups per tile
#define THREADS  768
#define SLOTS    28                // per-group slot pitch: [x0, X_0..X_19, pad]
#define XROW     (GN*SLOTS)        // 224 floats per k row
#define WPITCH   196               // 192 rows + 4 pad (float4-aligned rows)

#define XS_FLOATS (XD_*XROW)                  // 28672
#define WS_OFF    XS_FLOATS
#define SMEM_FLOATS (XS_FLOATS + XD_*WPITCH)  // 53760 floats = 215040 B

#define CTAS_PER_C 37
#define TILES_PER_C (B_*NP_/GN)    // 512

union F2U { float2 f; unsigned long long u; };
union F4U { float4 f; unsigned long long u[2]; float s[4]; };

// packed f32x2 FMA (Blackwell PTX-only pattern)
#define FMA2(acc, a2, b2) \
    asm("fma.rn.f32x2 %0, %1, %2, %0;" : "+l"(acc) : "l"(a2), "l"(b2))

__device__ __forceinline__ unsigned long long pk2(float lo, float hi) {
    unsigned long long r;
    asm("mov.b64 %0, {%1, %2};" : "=l"(r) : "f"(lo), "f"(hi));
    return r;
}

extern __shared__ float smem[];

__global__ __launch_bounds__(THREADS, 1)
void fista_gemm(const float* __restrict__ X, const float* __restrict__ x0,
                const float* __restrict__ A, const float* __restrict__ Cm,
                float* __restrict__ out)
{
    const int c    = blockIdx.x / CTAS_PER_C;
    const int slot = blockIdx.x % CTAS_PER_C;
    const int tid  = threadIdx.x;

    float* xs = smem;            // xs[k][g][s]  (pitch: k->224, g->28)
    float* Ws = smem + WS_OFF;   // Ws[k][m]     (pitch 196; m 0..127=A rows, 128..191=C rows)

    // ---- stage W = [A_c ; C_c] transposed (once per persistent CTA) ----
    for (int idx = tid; idx < 192*XD_; idx += THREADS) {
        int m = idx >> 7, k = idx & 127;
        float v = (m < 128) ? A [c*XD_*XD_ + m*XD_ + k]
                            : Cm[c*PD_*XD_ + (m-128)*XD_ + k];
        Ws[k*WPITCH + m] = v;
    }

    // thread -> micro-tile mapping (warp-uniform pred/recon split)
    const int gx   = tid & 15;          // 16 n-groups
    const int gy   = tid >> 4;          // 48 m-groups
    const int g    = gx >> 1;           // (b,p) group within tile
    const int t0   = (gx & 1) * 10;     // first of 10 time columns
    const bool is_pred = (gy < 32);
    const int row0 = is_pred ? gy*4 : 128 + (gy-32)*4;
    const int i0   = row0 - 128;        // recon row base

    #pragma unroll 1
    for (int tt = slot; tt < TILES_PER_C; tt += CTAS_PER_C) {
        __syncthreads();  // prior tile compute done (and W staging on iter 0)

        // ---- stage X tile: 8 groups x (x0 + 128x20) ----
        for (int idx = tid; idx < GN*XD_*T_; idx += THREADS) {
            int gg  = idx / (XD_*T_);
            int rem = idx - gg*(XD_*T_);
            int j   = rem / T_;
            int t   = rem - j*T_;
            int pg  = tt*GN + gg;
            int bc  = (pg >> 8)*C_ + c;
            int p   = pg & 255;
            xs[j*XROW + gg*SLOTS + 1 + t] = X[((bc*NP_ + p)*XD_ + j)*T_ + t];
        }
        for (int idx = tid; idx < GN*XD_; idx += THREADS) {
            int gg = idx >> 7, j = idx & 127;
            int pg = tt*GN + gg;
            int bc = (pg >> 8)*C_ + c;
            int p  = pg & 255;
            xs[j*XROW + gg*SLOTS] = x0[(bc*NP_ + p)*XD_ + j];
        }
        __syncthreads();

        unsigned long long acc2[20];
        #pragma unroll
        for (int q = 0; q < 20; q++) acc2[q] = 0ull;

        const float* xbase = xs + g*SLOTS;
        const float* wbase = Ws + row0;

        if (is_pred) {
            // pred: acc2[r*5+q] = cols (t0+2q, t0+2q+1) of row row0+r
            #pragma unroll 2
            for (int k = 0; k < XD_; k++) {
                F4U w; w.f = *(const float4*)(wbase + k*WPITCH);
                unsigned long long a0 = pk2(w.s[0], w.s[0]);
                unsigned long long a1 = pk2(w.s[1], w.s[1]);
                unsigned long long a2 = pk2(w.s[2], w.s[2]);
                unsigned long long a3 = pk2(w.s[3], w.s[3]);
                const float* xk = xbase + k*XROW + t0;   // prev: slot t = col t
                #pragma unroll
                for (int q = 0; q < 5; q++) {
                    F2U b; b.f = *(const float2*)(xk + 2*q);
                    FMA2(acc2[q],      a0, b.u);
                    FMA2(acc2[5+q],    a1, b.u);
                    FMA2(acc2[10+q],   a2, b.u);
                    FMA2(acc2[15+q],   a3, b.u);
                }
            }
            // epilogue: X_pred (contiguous float2 stores)
            const int pg = tt*GN + g;
            const int bc = (pg >> 8)*C_ + c;
            const int p  = pg & 255;
            const int base = XPRED_OFF + ((bc*NP_ + p)*XD_ + row0)*T_ + t0;
            #pragma unroll
            for (int r = 0; r < 4; r++) {
                float2* dst = (float2*)(out + base + r*T_);
                #pragma unroll
                for (int q = 0; q < 5; q++) {
                    F2U o; o.u = acc2[r*5 + q];
                    dst[q] = o.f;
                }
            }
        } else {
            // recon: acc2[rp*10+q] = col t0+q of rows (i0+2rp, i0+2rp+1)
            #pragma unroll 2
            for (int k = 0; k < XD_; k++) {
                F4U w; w.f = *(const float4*)(wbase + k*WPITCH);
                const float* xk = xbase + k*XROW + t0 + 1;  // X_t at slot t+1
                #pragma unroll
                for (int q = 0; q < 10; q++) {
                    float bv = xk[q];
                    unsigned long long b2 = pk2(bv, bv);
                    FMA2(acc2[q],    w.u[0], b2);
                    FMA2(acc2[10+q], w.u[1], b2);
                }
            }
            // epilogue: img (pixel-shuffle scatter)
            const int pg  = tt*GN + g;
            const int bc  = (pg >> 8)*C_ + c;
            const int p   = pg & 255;
            const int gyy = p >> 4, gxx = p & 15;
            #pragma unroll
            for (int rp = 0; rp < 2; rp++) {
                #pragma unroll
                for (int half = 0; half < 2; half++) {
                    int i  = i0 + 2*rp + half;
                    int py = i >> 3, px = i & 7;
                    float* dst = out + ((bc*128 + gyy*8 + py)*128 + gxx*8 + px)*T_ + t0;
                    #pragma unroll
                    for (int q = 0; q < 10; q++) {
                        F2U o; o.u = acc2[rp*10 + q];
                        dst[q] = half ? o.f.y : o.f.x;
                    }
                }
            }
        }
    }
}

// ---------------- X_U (memory-bound, deterministic serial sums) ----------------
__global__ __launch_bounds__(256)
void fista_xu(const float* __restrict__ X, const float* __restrict__ U,
              const float* __restrict__ Bm, float* __restrict__ out)
{
    const int idx = blockIdx.x * blockDim.x + threadIdx.x;  // [0, 163840)
    const int t  = idx % T_;
    const int i  = (idx / T_) & (XD_-1);
    const int bc = idx / (XD_*T_);
    const int c  = bc & (C_-1);

    const float* xptr = X + (long)bc*NP_*XD_*T_ + i*T_ + t;
    float S = 0.f;
    #pragma unroll 8
    for (int p = 0; p < NP_; p++) S += fabsf(__ldg(xptr + (long)p*XD_*T_));

    const float* uptr = U + bc*UD_*T_ + t;
    const float* brow = Bm + (c*XD_ + i)*UD_;
    float bu = 0.f;
    #pragma unroll
    for (int j = 0; j < UD_; j++) bu += brow[j] * uptr[j*T_];

    out[XU_OFF + idx] = 0.05f * (1.f + expf(-bu)) * S;
}

extern "C" void kernel_launch(void* const* d_in, const int* in_sizes, int n_in,
                              void* d_out, int out_size)
{
    const float* X  = (const float*)d_in[0];
    const float* U  = (const float*)d_in[1];
    const float* x0 = (const float*)d_in[2];
    const float* A  = (const float*)d_in[3];
    const float* Bm = (const float*)d_in[4];
    const float* Cm = (const float*)d_in[5];
    float* out = (float*)d_out;

    cudaFuncSetAttribute(fista_gemm, cudaFuncAttributeMaxDynamicSharedMemorySize,
                         SMEM_FLOATS * (int)sizeof(float));

    fista_gemm<<<C_*CTAS_PER_C, THREADS, SMEM_FLOATS*sizeof(float)>>>(X, x0, A, Cm, out);
    fista_xu<<<(B_*C_*XD_*T_)/256, 256>>>(X, U, Bm, out);
}